// round 6
// baseline (speedup 1.0000x reference)
#include <cuda_runtime.h>
#include <math_constants.h>
#include <cstdint>

#define BB 8
#define NN 4096
#define DD 16
#define OO 64
#define KK 20
#define KP 24            // per-split fast-pass pad
#define SPLIT 8          // candidate splits per query
#define QTR (NN/SPLIT)   // 512 candidates per split
#define CNT (8LL*4096*20)

#define THR 64           // threads per knn block
#define QPB 128          // queries per knn block (2 per thread)
#define TC 128           // candidate tile rows
#define BUFCAP 192       // per-query pending buffer (local mem)

// ---------------- scratch (static device globals: no allocation) ------------
__device__ float  g_u[BB*NN*OO];
__device__ float  g_v[BB*NN*OO];
__device__ int    g_idx[BB*NN*KK];          // final knn indices
__device__ int    g_pidx[BB*NN*SPLIT*KP];   // per-split fast top-24 indices
__device__ float  g_sqf[BB*NN];             // XLA-emulated fp32 sum(x*x)
__device__ double g_sum[OO];
__device__ double g_sumsq[OO];
__device__ float  g_a[OO];
__device__ float  g_c[OO];

// ---------------- f32x2 packed helpers (PTX) ---------------------------------
__device__ __forceinline__ unsigned long long pk2(float lo, float hi) {
    unsigned long long r;
    asm("mov.b64 %0, {%1, %2};" : "=l"(r) : "f"(lo), "f"(hi));
    return r;
}
__device__ __forceinline__ void upk2(unsigned long long v, float& lo, float& hi) {
    asm("mov.b64 {%0, %1}, %2;" : "=f"(lo), "=f"(hi) : "l"(v));
}
__device__ __forceinline__ unsigned long long fma2(unsigned long long a,
                                                   unsigned long long b,
                                                   unsigned long long c) {
    unsigned long long d;
    asm("fma.rn.f32x2 %0, %1, %2, %3;" : "=l"(d) : "l"(a), "l"(b), "l"(c));
    return d;
}
__device__ __forceinline__ unsigned long long mul2(unsigned long long a,
                                                   unsigned long long b) {
    unsigned long long d;
    asm("mul.rn.f32x2 %0, %1, %2;" : "=l"(d) : "l"(a), "l"(b));
    return d;
}
__device__ __forceinline__ unsigned long long add2(unsigned long long a,
                                                   unsigned long long b) {
    unsigned long long d;
    asm("add.rn.f32x2 %0, %1, %2;" : "=l"(d) : "l"(a), "l"(b));
    return d;
}

// ---------------- kernel 0: zero accumulators --------------------------------
__global__ void zero_sums() {
    int t = threadIdx.x;
    if (t < OO) { g_sum[t] = 0.0; g_sumsq[t] = 0.0; }
}

// ---------------- kernel 0b: XLA-emulated per-point squared norms -----------
// DO NOT CHANGE (bit-exact emulation of reference rounding; validated R3).
__global__ void sq_kernel(const float* __restrict__ x) {
    int p = blockIdx.x * blockDim.x + threadIdx.x;
    const float4* xp = (const float4*)(x + (size_t)p * DD);
    float s[4];
#pragma unroll
    for (int i = 0; i < 4; i++) {
        float4 v = xp[i];
        float a = __fmul_rn(v.x, v.x);
        a = __fadd_rn(a, __fmul_rn(v.y, v.y));
        a = __fadd_rn(a, __fmul_rn(v.z, v.z));
        a = __fadd_rn(a, __fmul_rn(v.w, v.w));
        s[i] = a;
    }
    g_sqf[p] = __fadd_rn(__fadd_rn(s[0], s[2]), __fadd_rn(s[1], s[3]));
}

// ---------------- kernel 1: per-point projections u, v ----------------------
__global__ void proj_kernel(const float* __restrict__ x,
                            const float* __restrict__ W) {
    __shared__ float Wt[2*DD][OO];
    __shared__ float xr[4][DD];
    int tid = threadIdx.x;
    for (int i = tid; i < OO*2*DD; i += blockDim.x) {
        int o = i / (2*DD), c = i % (2*DD);
        Wt[c][o] = W[i];
    }
    int p0 = blockIdx.x * 4;
    if (tid < 4*DD) xr[tid >> 4][tid & 15] = x[p0*DD + tid];
    __syncthreads();
    int o  = tid & 63;
    int nl = tid >> 6;
    float cacc = 0.f, facc = 0.f;
#pragma unroll
    for (int d = 0; d < DD; d++) {
        float xv = xr[nl][d];
        cacc = fmaf(Wt[d][o],      xv, cacc);
        facc = fmaf(Wt[DD + d][o], xv, facc);
    }
    int p = p0 + nl;
    g_u[p*OO + o] = cacc - facc;
    g_v[p*OO + o] = facc;
}

// ---------------- kNN select helpers -----------------------------------------
// stable insertion by strict '<' == order by (d asc, idx asc), since arrivals
// are in ascending idx within a split. Rare path.
__device__ void compactf(float* __restrict__ bd, int* __restrict__ bi, int& cnt,
                         float* __restrict__ hd, int* __restrict__ hi,
                         float& thr) {
    float worst = hd[KP-1];
    for (int i = 0; i < cnt; i++) {
        float d = bd[i];
        if (d < worst) {
            int idx = bi[i];
            int j = KP - 1;
            while (j > 0 && d < hd[j-1]) {
                hd[j] = hd[j-1]; hi[j] = hi[j-1]; j--;
            }
            hd[j] = d; hi[j] = idx;
            worst = hd[KP-1];
        }
    }
    cnt = 0;
    thr = worst;
}

// ---------------- kernel 2a: fast-pass kNN (f32x2, branchless push) ---------
// grid = BB * (NN/QPB) * SPLIT blocks of 64 threads; 2 queries per thread.
// Tile stores candidates duplicated (c,c), pre-scaled by -2, so the packed
// score is d2' = (sq_c - 2*qA.c, sq_c - 2*qB.c) = d2 - sq_q (order-equiv).
__global__ __launch_bounds__(THR, 12) void knn_part_kernel(const float* __restrict__ x) {
    __shared__ unsigned long long xs2[TC*16];   // (c_d, c_d) per row, per dim
    __shared__ unsigned long long sqs2[TC];     // (s, s)

    int tid   = threadIdx.x;
    int split = blockIdx.x & (SPLIT-1);
    int qg    = (blockIdx.x >> 3) & 31;
    int b     = blockIdx.x >> 8;
    int qn0   = qg * QPB + tid;
    int qn1   = qn0 + THR;
    int cbase = split * QTR;

    const float* xb  = x + (size_t)b * NN * DD;
    const float* sqb = g_sqf + (size_t)b * NN;

    // packed queries: q[d] = (A_d, B_d)
    unsigned long long q[16];
    {
        const float* qa = xb + (size_t)qn0 * DD;
        const float* qb_ = xb + (size_t)qn1 * DD;
#pragma unroll
        for (int d = 0; d < 16; d++) q[d] = pk2(qa[d], qb_[d]);
    }

    float hd0[KP], hd1[KP];
    int   hi0[KP], hi1[KP];
#pragma unroll
    for (int j = 0; j < KP; j++) {
        hd0[j] = CUDART_INF_F; hd1[j] = CUDART_INF_F;
        hi0[j] = 0; hi1[j] = 0;
    }
    float bd0[BUFCAP], bd1[BUFCAP];
    int   bi0[BUFCAP], bi1[BUFCAP];
    int cnt0 = 0, cnt1 = 0;
    float thr0 = CUDART_INF_F, thr1 = CUDART_INF_F;

    for (int t0 = 0; t0 < QTR; t0 += TC) {
        // stage tile: duplicated, scaled by -2; linear u64 mapping (no conflicts)
        for (int e = tid; e < TC*16; e += THR) {
            int row = e >> 4, d = e & 15;
            float v = -2.f * xb[(size_t)(cbase + t0 + row) * DD + d];
            xs2[e] = pk2(v, v);
        }
#pragma unroll
        for (int j = 0; j < TC/THR; j++) {
            int r = tid + j * THR;
            float s = sqb[cbase + t0 + r];
            sqs2[r] = pk2(s, s);
        }
        __syncthreads();

#pragma unroll 2
        for (int m = 0; m < TC; m++) {
            const ulonglong2* row = (const ulonglong2*)&xs2[m*16];
            ulonglong2 r0 = row[0], r1 = row[1], r2 = row[2], r3 = row[3];
            ulonglong2 r4 = row[4], r5 = row[5], r6 = row[6], r7 = row[7];
            unsigned long long a0 = fma2(q[0],  r0.x, sqs2[m]);
            unsigned long long a1 = mul2(q[1],  r0.y);
            unsigned long long a2 = mul2(q[2],  r1.x);
            unsigned long long a3 = mul2(q[3],  r1.y);
            a0 = fma2(q[4],  r2.x, a0); a1 = fma2(q[5],  r2.y, a1);
            a2 = fma2(q[6],  r3.x, a2); a3 = fma2(q[7],  r3.y, a3);
            a0 = fma2(q[8],  r4.x, a0); a1 = fma2(q[9],  r4.y, a1);
            a2 = fma2(q[10], r5.x, a2); a3 = fma2(q[11], r5.y, a3);
            a0 = fma2(q[12], r6.x, a0); a1 = fma2(q[13], r6.y, a1);
            a2 = fma2(q[14], r7.x, a2); a3 = fma2(q[15], r7.y, a3);
            unsigned long long d2 = add2(add2(a0, a1), add2(a2, a3));
            float dA, dB;
            upk2(d2, dA, dB);

            int gi = cbase + t0 + m;
            // branchless: unconditional store, predicated advance
            bd0[cnt0] = dA; bi0[cnt0] = gi; cnt0 += (dA < thr0) ? 1 : 0;
            bd1[cnt1] = dB; bi1[cnt1] = gi; cnt1 += (dB < thr1) ? 1 : 0;
        }
        __syncthreads();

        if (cnt0 >= BUFCAP - TC) compactf(bd0, bi0, cnt0, hd0, hi0, thr0);
        if (cnt1 >= BUFCAP - TC) compactf(bd1, bi1, cnt1, hd1, hi1, thr1);
    }
    compactf(bd0, bi0, cnt0, hd0, hi0, thr0);
    compactf(bd1, bi1, cnt1, hd1, hi1, thr1);

    int* o0 = g_pidx + (((size_t)b * NN + qn0) * SPLIT + split) * KP;
    int* o1 = g_pidx + (((size_t)b * NN + qn1) * SPLIT + split) * KP;
#pragma unroll
    for (int j = 0; j < KP; j++) { o0[j] = hi0[j]; o1[j] = hi1[j]; }
}

// ---------------- kernel 2b: merge splits + emulated-reference refinement ---
// FROZEN numerics (validated R3): serial-FFMA dot k ascending;
// d2 = fl( fl(sqn + sqc) - fl(2*dot) ); u64 key = (monotone d2, idx).
#define TQM 64
__device__ __forceinline__ unsigned long long pack_key(float d, int gidx) {
    unsigned s = __float_as_uint(d);
    s ^= ((unsigned)((int)s >> 31)) | 0x80000000u;
    return ((unsigned long long)s << 32) | (unsigned)gidx;
}

__global__ __launch_bounds__(TQM) void knn_merge_kernel(const float* __restrict__ x) {
    int tid = threadIdx.x;
    int b   = blockIdx.x >> 6;
    int qn  = ((blockIdx.x & 63) << 6) + tid;
    const float* xb  = x + (size_t)b * NN * DD;
    const float* sqb = g_sqf + (size_t)b * NN;

    const float4* qp = (const float4*)(xb + (size_t)qn * DD);
    float4 q0 = qp[0], q1 = qp[1], q2 = qp[2], q3 = qp[3];
    float sqn = sqb[qn];

    unsigned long long outk[KK];
#pragma unroll
    for (int j = 0; j < KK; j++) outk[j] = 0xFFFFFFFFFFFFFFFFull;

    const int* pin = g_pidx + ((size_t)b * NN + qn) * SPLIT * KP;
#pragma unroll 4
    for (int j = 0; j < SPLIT * KP; j++) {
        int ci = pin[j];
        const float4* cp = (const float4*)(xb + (size_t)ci * DD);
        float4 c0 = cp[0], c1 = cp[1], c2 = cp[2], c3 = cp[3];
        float acc = 0.f;
        acc = fmaf(q0.x, c0.x, acc); acc = fmaf(q0.y, c0.y, acc);
        acc = fmaf(q0.z, c0.z, acc); acc = fmaf(q0.w, c0.w, acc);
        acc = fmaf(q1.x, c1.x, acc); acc = fmaf(q1.y, c1.y, acc);
        acc = fmaf(q1.z, c1.z, acc); acc = fmaf(q1.w, c1.w, acc);
        acc = fmaf(q2.x, c2.x, acc); acc = fmaf(q2.y, c2.y, acc);
        acc = fmaf(q2.z, c2.z, acc); acc = fmaf(q2.w, c2.w, acc);
        acc = fmaf(q3.x, c3.x, acc); acc = fmaf(q3.y, c3.y, acc);
        acc = fmaf(q3.z, c3.z, acc); acc = fmaf(q3.w, c3.w, acc);
        float ssum = __fadd_rn(sqn, sqb[ci]);
        float d2   = __fsub_rn(ssum, __fmul_rn(2.0f, acc));
        unsigned long long key = pack_key(d2, ci);
        if (key < outk[KK-1]) {
            outk[KK-1] = key;
#pragma unroll
            for (int t = KK-1; t > 0; --t) {
                if (outk[t] < outk[t-1]) {
                    unsigned long long tmp = outk[t];
                    outk[t] = outk[t-1]; outk[t-1] = tmp;
                } else break;
            }
        }
    }

    int* outp = g_idx + ((size_t)b * NN + qn) * KK;
#pragma unroll
    for (int j = 0; j < KK; j++) outp[j] = (int)(outk[j] & 0xFFFFFFFFu);
}

// ---------------- kernel 3: per-channel sum / sumsq over (b,n,k) ------------
__global__ void sums_kernel() {
    int tid = threadIdx.x;
    int o = tid & 63;
    int g = tid >> 6;
    float s = 0.f, s2 = 0.f;
    int r0 = (blockIdx.x * 4 + g) * 32;
    for (int i = 0; i < 32; i++) {
        int r = r0 + i;
        int b = r >> 12;
        float u = g_u[(size_t)r * OO + o];
        const int* ip = g_idx + (size_t)r * KK;
#pragma unroll
        for (int k = 0; k < KK; k++) {
            int gi = ip[k];
            float h = u + g_v[(((size_t)b << 12) + gi) * OO + o];
            s += h;
            s2 = fmaf(h, h, s2);
        }
    }
    atomicAdd(&g_sum[o],   (double)s);
    atomicAdd(&g_sumsq[o], (double)s2);
}

// ---------------- kernel 4: finalize affine coefficients --------------------
__global__ void finalize_kernel(const float* __restrict__ gamma,
                                const float* __restrict__ beta) {
    int o = threadIdx.x;
    if (o < OO) {
        double mean = g_sum[o] / (double)CNT;
        double var  = g_sumsq[o] / (double)CNT - mean * mean;
        double rstd = 1.0 / sqrt(var + 1e-5);
        float a = gamma[o] * (float)rstd;
        g_a[o] = a;
        g_c[o] = fmaf(-(float)mean, a, beta[o]);
    }
}

// ---------------- kernel 5: write output (coalesced, smem-staged) -----------
__global__ void out_kernel(float* __restrict__ out) {
    __shared__ float su[NN];
    __shared__ float sv[NN];
    int b = blockIdx.x >> 6;
    int o = blockIdx.x & 63;
    float a = g_a[o], c = g_c[o];
    int tid = threadIdx.x;
    size_t base = (size_t)b * NN * OO;
    for (int i = tid; i < NN; i += blockDim.x) {
        su[i] = fmaf(a, g_u[base + (size_t)i * OO + o], c);
        sv[i] = a * g_v[base + (size_t)i * OO + o];
    }
    __syncthreads();
    const int* ip = g_idx + (size_t)b * NN * KK;
    float* op = out + (size_t)blockIdx.x * (NN * KK);
    for (int e = tid; e < NN * KK; e += blockDim.x) {
        int n = e / KK;
        int gi = ip[e];
        float y = su[n] + sv[gi];
        op[e] = fmaxf(y, 0.f);
    }
}

// ---------------- launcher ---------------------------------------------------
extern "C" void kernel_launch(void* const* d_in, const int* in_sizes, int n_in,
                              void* d_out, int out_size) {
    const float* x     = (const float*)d_in[0];
    const float* W     = (const float*)d_in[1];
    const float* gamma = (const float*)d_in[2];
    const float* beta  = (const float*)d_in[3];
    float* out = (float*)d_out;

    zero_sums<<<1, 64>>>();
    sq_kernel<<<BB*NN/256, 256>>>(x);
    proj_kernel<<<BB*NN/4, 256>>>(x, W);
    knn_part_kernel<<<BB*(NN/QPB)*SPLIT, THR>>>(x);
    knn_merge_kernel<<<BB*NN/TQM, TQM>>>(x);
    sums_kernel<<<BB*NN/128, 256>>>();
    finalize_kernel<<<1, 64>>>(gamma, beta);
    out_kernel<<<BB*OO, 256>>>(out);
}

// round 7
// speedup vs baseline: 2.7758x; 2.7758x over previous
#include <cuda_runtime.h>
#include <math_constants.h>
#include <cstdint>

#define BB 8
#define NN 4096
#define DD 16
#define OO 64
#define KK 20
#define KP 24            // per-split fast-pass pad
#define SPLIT 4          // candidate splits per query
#define QTR (NN/SPLIT)   // 1024 candidates per split
#define CNT (8LL*4096*20)

#define THR 128          // threads per knn block = queries per block
#define TC 256           // candidate tile rows
#define TP (TC/2)        // candidate pairs per tile
#define BUFCAP 320       // per-thread pending buffer (local mem)

// ---------------- scratch (static device globals: no allocation) ------------
__device__ float  g_u[BB*NN*OO];
__device__ float  g_v[BB*NN*OO];
__device__ int    g_idx[BB*NN*KK];          // final knn indices
__device__ int    g_pidx[BB*NN*SPLIT*KP];   // per-split fast top-24 indices
__device__ float  g_sqf[BB*NN];             // XLA-emulated fp32 sum(x*x)
__device__ double g_sum[OO];
__device__ double g_sumsq[OO];
__device__ float  g_a[OO];
__device__ float  g_c[OO];

// ---------------- f32x2 packed helpers (PTX) ---------------------------------
__device__ __forceinline__ unsigned long long pk2(float lo, float hi) {
    unsigned long long r;
    asm("mov.b64 %0, {%1, %2};" : "=l"(r) : "f"(lo), "f"(hi));
    return r;
}
__device__ __forceinline__ void upk2(unsigned long long v, float& lo, float& hi) {
    asm("mov.b64 {%0, %1}, %2;" : "=f"(lo), "=f"(hi) : "l"(v));
}
__device__ __forceinline__ unsigned long long fma2(unsigned long long a,
                                                   unsigned long long b,
                                                   unsigned long long c) {
    unsigned long long d;
    asm("fma.rn.f32x2 %0, %1, %2, %3;" : "=l"(d) : "l"(a), "l"(b), "l"(c));
    return d;
}
__device__ __forceinline__ unsigned long long mul2(unsigned long long a,
                                                   unsigned long long b) {
    unsigned long long d;
    asm("mul.rn.f32x2 %0, %1, %2;" : "=l"(d) : "l"(a), "l"(b));
    return d;
}
__device__ __forceinline__ unsigned long long add2(unsigned long long a,
                                                   unsigned long long b) {
    unsigned long long d;
    asm("add.rn.f32x2 %0, %1, %2;" : "=l"(d) : "l"(a), "l"(b));
    return d;
}

// predicated push: 1 SETP + predicated ST + predicated IADD. No branch, no
// LSU dispatch when the predicate is false.
__device__ __forceinline__ void push(unsigned long long* buf, int& cnt,
                                     float d, float thr, int gi) {
    unsigned long long key;
    asm("mov.b64 %0, {%1, %2};" : "=l"(key) : "f"(d), "r"(gi));   // lo=d, hi=gi
    unsigned long long* addr = buf + cnt;
    asm volatile("{\n\t"
        ".reg .pred p;\n\t"
        "setp.lt.f32 p, %1, %2;\n\t"
        "@p st.u64 [%3], %4;\n\t"
        "@p add.s32 %0, %0, 1;\n\t"
        "}" : "+r"(cnt)
        : "f"(d), "f"(thr), "l"(addr), "l"(key) : "memory");
}

// ---------------- kernel 0: zero accumulators --------------------------------
__global__ void zero_sums() {
    int t = threadIdx.x;
    if (t < OO) { g_sum[t] = 0.0; g_sumsq[t] = 0.0; }
}

// ---------------- kernel 0b: XLA-emulated per-point squared norms -----------
// DO NOT CHANGE (bit-exact emulation of reference rounding; validated R3).
__global__ void sq_kernel(const float* __restrict__ x) {
    int p = blockIdx.x * blockDim.x + threadIdx.x;
    const float4* xp = (const float4*)(x + (size_t)p * DD);
    float s[4];
#pragma unroll
    for (int i = 0; i < 4; i++) {
        float4 v = xp[i];
        float a = __fmul_rn(v.x, v.x);
        a = __fadd_rn(a, __fmul_rn(v.y, v.y));
        a = __fadd_rn(a, __fmul_rn(v.z, v.z));
        a = __fadd_rn(a, __fmul_rn(v.w, v.w));
        s[i] = a;
    }
    g_sqf[p] = __fadd_rn(__fadd_rn(s[0], s[2]), __fadd_rn(s[1], s[3]));
}

// ---------------- kernel 1: per-point projections u, v ----------------------
__global__ void proj_kernel(const float* __restrict__ x,
                            const float* __restrict__ W) {
    __shared__ float Wt[2*DD][OO];
    __shared__ float xr[4][DD];
    int tid = threadIdx.x;
    for (int i = tid; i < OO*2*DD; i += blockDim.x) {
        int o = i / (2*DD), c = i % (2*DD);
        Wt[c][o] = W[i];
    }
    int p0 = blockIdx.x * 4;
    if (tid < 4*DD) xr[tid >> 4][tid & 15] = x[p0*DD + tid];
    __syncthreads();
    int o  = tid & 63;
    int nl = tid >> 6;
    float cacc = 0.f, facc = 0.f;
#pragma unroll
    for (int d = 0; d < DD; d++) {
        float xv = xr[nl][d];
        cacc = fmaf(Wt[d][o],      xv, cacc);
        facc = fmaf(Wt[DD + d][o], xv, facc);
    }
    int p = p0 + nl;
    g_u[p*OO + o] = cacc - facc;
    g_v[p*OO + o] = facc;
}

// ---------------- kNN select: rare-path compaction ---------------------------
// stable strict-'<' insertion == (d asc, idx asc) since buffer is scan-ordered.
__device__ void compactf(unsigned long long* __restrict__ buf, int& cnt,
                         float* __restrict__ hd, int* __restrict__ hi,
                         float& thr) {
    float worst = hd[KP-1];
    for (int i = 0; i < cnt; i++) {
        unsigned long long e = buf[i];
        float d = __uint_as_float((unsigned)(e & 0xFFFFFFFFu));
        if (d < worst) {
            int idx = (int)(e >> 32);
            int j = KP - 1;
            while (j > 0 && d < hd[j-1]) { hd[j] = hd[j-1]; hi[j] = hi[j-1]; j--; }
            hd[j] = d; hi[j] = idx;
            worst = hd[KP-1];
        }
    }
    cnt = 0;
    thr = worst;
}

// ---------------- kernel 2a: fast-pass kNN -----------------------------------
// 1 query/thread, candidate PAIRS packed in f32x2. Tile stores (-2*cA, -2*cB)
// per dim; score d' = sq_c - 2*q.c = d2 - sq_q (rank-equivalent per query).
// grid = BB * (NN/THR) * SPLIT = 1024 blocks of 128 threads.
__global__ __launch_bounds__(THR, 5) void knn_part_kernel(const float* __restrict__ x) {
    __shared__ ulonglong2 xs2[TP*8];            // [pair][dim/2], 16KB
    __shared__ unsigned long long sq2[TP];      // (sq_even, sq_odd), 1KB

    int tid   = threadIdx.x;
    int split = blockIdx.x & (SPLIT-1);
    int qg    = (blockIdx.x >> 2) & 31;
    int b     = blockIdx.x >> 7;
    int qn    = qg * THR + tid;
    int cbase = split * QTR;

    const float* xb  = x + (size_t)b * NN * DD;
    const float* sqb = g_sqf + (size_t)b * NN;

    // query broadcast-packed: qq[d] = (q_d, q_d)
    unsigned long long qq[16];
    {
        const float* qp = xb + (size_t)qn * DD;
#pragma unroll
        for (int d = 0; d < 16; d++) qq[d] = pk2(qp[d], qp[d]);
    }

    float hd[KP]; int hi[KP];                   // local mem (rare access)
#pragma unroll
    for (int j = 0; j < KP; j++) { hd[j] = CUDART_INF_F; hi[j] = 0; }
    unsigned long long buf[BUFCAP];             // local mem pending buffer
    int cnt = 0;
    float thr = CUDART_INF_F;

    for (int t0 = 0; t0 < QTR; t0 += TC) {
        // stage tile: pairs, scaled by -2
        unsigned long long* xsl = (unsigned long long*)xs2;
        for (int e = tid; e < TP*16; e += THR) {
            int pr = e >> 4, d = e & 15;
            int r = cbase + t0 + 2*pr;
            float vA = -2.f * xb[(size_t)r * DD + d];
            float vB = -2.f * xb[(size_t)(r+1) * DD + d];
            xsl[pr*16 + d] = pk2(vA, vB);
        }
        {
            int r = cbase + t0 + 2*tid;
            sq2[tid] = pk2(sqb[r], sqb[r+1]);
        }
        __syncthreads();

#pragma unroll 2
        for (int m = 0; m < TP; m++) {
            ulonglong2 r0 = xs2[m*8+0], r1 = xs2[m*8+1];
            ulonglong2 r2 = xs2[m*8+2], r3 = xs2[m*8+3];
            ulonglong2 r4 = xs2[m*8+4], r5 = xs2[m*8+5];
            ulonglong2 r6 = xs2[m*8+6], r7 = xs2[m*8+7];
            unsigned long long a0 = fma2(qq[0], r0.x, sq2[m]);
            unsigned long long a1 = mul2(qq[1], r0.y);
            unsigned long long a2 = mul2(qq[2], r1.x);
            unsigned long long a3 = mul2(qq[3], r1.y);
            a0 = fma2(qq[4],  r2.x, a0); a1 = fma2(qq[5],  r2.y, a1);
            a2 = fma2(qq[6],  r3.x, a2); a3 = fma2(qq[7],  r3.y, a3);
            a0 = fma2(qq[8],  r4.x, a0); a1 = fma2(qq[9],  r4.y, a1);
            a2 = fma2(qq[10], r5.x, a2); a3 = fma2(qq[11], r5.y, a3);
            a0 = fma2(qq[12], r6.x, a0); a1 = fma2(qq[13], r6.y, a1);
            a2 = fma2(qq[14], r7.x, a2); a3 = fma2(qq[15], r7.y, a3);
            unsigned long long dd = add2(add2(a0, a1), add2(a2, a3));
            float dA, dB;
            upk2(dd, dA, dB);
            int gi = cbase + t0 + 2*m;
            push(buf, cnt, dA, thr, gi);
            push(buf, cnt, dB, thr, gi + 1);
        }
        __syncthreads();

        if (cnt >= BUFCAP - TC) compactf(buf, cnt, hd, hi, thr);
    }
    compactf(buf, cnt, hd, hi, thr);

    int* o = g_pidx + (((size_t)b * NN + qn) * SPLIT + split) * KP;
#pragma unroll
    for (int j = 0; j < KP; j++) o[j] = hi[j];
}

// ---------------- kernel 2b: merge splits + emulated-reference refinement ---
// FROZEN numerics (validated R3): serial-FFMA dot k ascending;
// d2 = fl( fl(sqn + sqc) - fl(2*dot) ); u64 key = (monotone d2, idx).
#define TQM 64
__device__ __forceinline__ unsigned long long pack_key(float d, int gidx) {
    unsigned s = __float_as_uint(d);
    s ^= ((unsigned)((int)s >> 31)) | 0x80000000u;
    return ((unsigned long long)s << 32) | (unsigned)gidx;
}

__global__ __launch_bounds__(TQM) void knn_merge_kernel(const float* __restrict__ x) {
    int tid = threadIdx.x;
    int b   = blockIdx.x >> 6;
    int qn  = ((blockIdx.x & 63) << 6) + tid;
    const float* xb  = x + (size_t)b * NN * DD;
    const float* sqb = g_sqf + (size_t)b * NN;

    const float4* qp = (const float4*)(xb + (size_t)qn * DD);
    float4 q0 = qp[0], q1 = qp[1], q2 = qp[2], q3 = qp[3];
    float sqn = sqb[qn];

    unsigned long long outk[KK];
#pragma unroll
    for (int j = 0; j < KK; j++) outk[j] = 0xFFFFFFFFFFFFFFFFull;

    const int* pin = g_pidx + ((size_t)b * NN + qn) * SPLIT * KP;
#pragma unroll 4
    for (int j = 0; j < SPLIT * KP; j++) {
        int ci = pin[j];
        const float4* cp = (const float4*)(xb + (size_t)ci * DD);
        float4 c0 = cp[0], c1 = cp[1], c2 = cp[2], c3 = cp[3];
        float acc = 0.f;
        acc = fmaf(q0.x, c0.x, acc); acc = fmaf(q0.y, c0.y, acc);
        acc = fmaf(q0.z, c0.z, acc); acc = fmaf(q0.w, c0.w, acc);
        acc = fmaf(q1.x, c1.x, acc); acc = fmaf(q1.y, c1.y, acc);
        acc = fmaf(q1.z, c1.z, acc); acc = fmaf(q1.w, c1.w, acc);
        acc = fmaf(q2.x, c2.x, acc); acc = fmaf(q2.y, c2.y, acc);
        acc = fmaf(q2.z, c2.z, acc); acc = fmaf(q2.w, c2.w, acc);
        acc = fmaf(q3.x, c3.x, acc); acc = fmaf(q3.y, c3.y, acc);
        acc = fmaf(q3.z, c3.z, acc); acc = fmaf(q3.w, c3.w, acc);
        float ssum = __fadd_rn(sqn, sqb[ci]);
        float d2   = __fsub_rn(ssum, __fmul_rn(2.0f, acc));
        unsigned long long key = pack_key(d2, ci);
        if (key < outk[KK-1]) {
            outk[KK-1] = key;
#pragma unroll
            for (int t = KK-1; t > 0; --t) {
                if (outk[t] < outk[t-1]) {
                    unsigned long long tmp = outk[t];
                    outk[t] = outk[t-1]; outk[t-1] = tmp;
                } else break;
            }
        }
    }

    int* outp = g_idx + ((size_t)b * NN + qn) * KK;
#pragma unroll
    for (int j = 0; j < KK; j++) outp[j] = (int)(outk[j] & 0xFFFFFFFFu);
}

// ---------------- kernel 3: per-channel sum / sumsq over (b,n,k) ------------
__global__ void sums_kernel() {
    int tid = threadIdx.x;
    int o = tid & 63;
    int g = tid >> 6;
    float s = 0.f, s2 = 0.f;
    int r0 = (blockIdx.x * 4 + g) * 32;
    for (int i = 0; i < 32; i++) {
        int r = r0 + i;
        int b = r >> 12;
        float u = g_u[(size_t)r * OO + o];
        const int* ip = g_idx + (size_t)r * KK;
#pragma unroll
        for (int k = 0; k < KK; k++) {
            int gi = ip[k];
            float h = u + g_v[(((size_t)b << 12) + gi) * OO + o];
            s += h;
            s2 = fmaf(h, h, s2);
        }
    }
    atomicAdd(&g_sum[o],   (double)s);
    atomicAdd(&g_sumsq[o], (double)s2);
}

// ---------------- kernel 4: finalize affine coefficients --------------------
__global__ void finalize_kernel(const float* __restrict__ gamma,
                                const float* __restrict__ beta) {
    int o = threadIdx.x;
    if (o < OO) {
        double mean = g_sum[o] / (double)CNT;
        double var  = g_sumsq[o] / (double)CNT - mean * mean;
        double rstd = 1.0 / sqrt(var + 1e-5);
        float a = gamma[o] * (float)rstd;
        g_a[o] = a;
        g_c[o] = fmaf(-(float)mean, a, beta[o]);
    }
}

// ---------------- kernel 5: write output (coalesced, smem-staged) -----------
__global__ void out_kernel(float* __restrict__ out) {
    __shared__ float su[NN];
    __shared__ float sv[NN];
    int b = blockIdx.x >> 6;
    int o = blockIdx.x & 63;
    float a = g_a[o], c = g_c[o];
    int tid = threadIdx.x;
    size_t base = (size_t)b * NN * OO;
    for (int i = tid; i < NN; i += blockDim.x) {
        su[i] = fmaf(a, g_u[base + (size_t)i * OO + o], c);
        sv[i] = a * g_v[base + (size_t)i * OO + o];
    }
    __syncthreads();
    const int* ip = g_idx + (size_t)b * NN * KK;
    float* op = out + (size_t)blockIdx.x * (NN * KK);
    for (int e = tid; e < NN * KK; e += blockDim.x) {
        int n = e / KK;
        int gi = ip[e];
        float y = su[n] + sv[gi];
        op[e] = fmaxf(y, 0.f);
    }
}

// ---------------- launcher ---------------------------------------------------
extern "C" void kernel_launch(void* const* d_in, const int* in_sizes, int n_in,
                              void* d_out, int out_size) {
    const float* x     = (const float*)d_in[0];
    const float* W     = (const float*)d_in[1];
    const float* gamma = (const float*)d_in[2];
    const float* beta  = (const float*)d_in[3];
    float* out = (float*)d_out;

    zero_sums<<<1, 64>>>();
    sq_kernel<<<BB*NN/256, 256>>>(x);
    proj_kernel<<<BB*NN/4, 256>>>(x, W);
    knn_part_kernel<<<BB*(NN/THR)*SPLIT, THR>>>(x);
    knn_merge_kernel<<<BB*NN/TQM, TQM>>>(x);
    sums_kernel<<<BB*NN/128, 256>>>();
    finalize_kernel<<<1, 64>>>(gamma, beta);
    out_kernel<<<BB*OO, 256>>>(out);
}